// round 11
// baseline (speedup 1.0000x reference)
#include <cuda_runtime.h>

// QCONVbk closed form:
//   out[b,f,h,w] = sum_c prod_{k=1..8} cos( patch_k(b,c,h,w) + weights[0,k] )
// (CNOT ring maps Z0 -> Z1..Z8 in the Heisenberg picture; RX product state
//  gives <Zq> = cos(a_q + w_q); the wire-0 angle drops out of <Z0>.)
//
// One thread per (pixel, channel) = 32768 threads; 4 consecutive lanes share a
// pixel, channel sum via 2x shfl_xor; each lane writes 2 of 8 filter copies.
// Branchless: clamped indices keep every load in-bounds; padding handled by
// post-load FSEL zeroing. Every warp executes the identical straight-line path.

#define BB 8
#define CC 4
#define HH 32
#define WW 32
#define FF 8

__global__ void __launch_bounds__(256) qconv_kernel(
    const float* __restrict__ x,      // (B, C, H, W)
    const float* __restrict__ wts,    // (1, 9)
    float* __restrict__ out)          // (B, 8, H, W)
{
    // start the (tiny) weight loads first; they overlap the x loads below
    const float4 wa  = __ldg((const float4*)(wts));       // wts[0..3]
    const float4 wb  = __ldg((const float4*)(wts + 4));   // wts[4..7]
    const float  wk8 = __ldg(&wts[8]);

    int tid = blockIdx.x * blockDim.x + threadIdx.x;   // 0 .. 32767
    int c   = tid & 3;
    int pix = tid >> 2;                                // 0 .. 8191
    int w = pix & (WW - 1);
    int h = (pix >> 5) & (HH - 1);
    int b = pix >> 10;

    // clamped row/col indices: all 8 loads always legal
    int hm = h << 5;
    int hu = max(h - 1, 0) << 5;
    int hd = min(h + 1, HH - 1) << 5;
    int wl = max(w - 1, 0);
    int wr = min(w + 1, WW - 1);

    const float* base = x + (((b * CC + c) << 10));

    float v1 = __ldg(base + hu + w );   // (-1, 0)
    float v2 = __ldg(base + hu + wr);   // (-1,+1)
    float v3 = __ldg(base + hm + wl);   // ( 0,-1)
    float v4 = __ldg(base + hm + w );   // ( 0, 0)
    float v5 = __ldg(base + hm + wr);   // ( 0,+1)
    float v6 = __ldg(base + hd + wl);   // (+1,-1)
    float v7 = __ldg(base + hd + w );   // (+1, 0)
    float v8 = __ldg(base + hd + wr);   // (+1,+1)

    // zero-padding masks, applied after the loads (FSEL, off the address path)
    bool bu = (h > 0), bd = (h < HH - 1);
    bool bl = (w > 0), br = (w < WW - 1);
    float a1 = bu         ? v1 : 0.0f;
    float a2 = (bu && br) ? v2 : 0.0f;
    float a3 = bl         ? v3 : 0.0f;
    float a4 = v4;
    float a5 = br         ? v5 : 0.0f;
    float a6 = (bd && bl) ? v6 : 0.0f;
    float a7 = bd         ? v7 : 0.0f;
    float a8 = (bd && br) ? v8 : 0.0f;

    float c1 = __cosf(a1 + wa.y);
    float c2 = __cosf(a2 + wa.z);
    float c3 = __cosf(a3 + wa.w);
    float c4 = __cosf(a4 + wb.x);
    float c5 = __cosf(a5 + wb.y);
    float c6 = __cosf(a6 + wb.z);
    float c7 = __cosf(a7 + wb.w);
    float c8 = __cosf(a8 + wk8);

    // pairwise product tree (depth 3)
    float p = ((c1 * c2) * (c3 * c4)) * ((c5 * c6) * (c7 * c8));

    // sum over the 4 channels held by 4 adjacent lanes
    p += __shfl_xor_sync(0xFFFFFFFFu, p, 1);
    p += __shfl_xor_sync(0xFFFFFFFFu, p, 2);

    // each lane writes 2 of the 8 identical filter copies
    float* ob = out + ((b << 13) + (h << 5) + w);
    ob[(size_t)(c    ) << 10] = p;
    ob[(size_t)(c + 4) << 10] = p;
}

extern "C" void kernel_launch(void* const* d_in, const int* in_sizes, int n_in,
                              void* d_out, int out_size) {
    const float* x   = (const float*)d_in[0];   // (8,4,32,32)
    const float* wts = (const float*)d_in[1];   // (1,9)
    float* out = (float*)d_out;                 // (8,8,32,32)
    (void)in_sizes; (void)n_in; (void)out_size;

    const int total_threads = BB * HH * WW * CC;   // 32768
    qconv_kernel<<<total_threads / 256, 256>>>(x, wts, out);
}